// round 1
// baseline (speedup 1.0000x reference)
#include <cuda_runtime.h>
#include <cuda_bf16.h>

#define B_    128
#define H_    14
#define W_    14
#define C_    512
#define NCLS_ 200
#define HWN_  196            // H*W
#define CCHUNK_ 128
#define THREADS_ 128
#define ROWSTRIDE_ 197       // 197 % 32 = 5, gcd(5,32)=1 -> conflict-free LDS

__global__ __launch_bounds__(THREADS_, 2)
void fused_masked_kernel(const float* __restrict__ x,
                         const float* __restrict__ gt,
                         const float* __restrict__ t_p,
                         const float* __restrict__ ct,
                         float* __restrict__ out) {
    extern __shared__ float smem_t[];      // [CCHUNK_][ROWSTRIDE_]
    __shared__ float sval[THREADS_];
    __shared__ int   sidx[THREADS_];
    __shared__ int   s_cls;

    const int b    = blockIdx.y;
    const int tid  = threadIdx.x;
    const int c    = blockIdx.x * CCHUNK_ + tid;
    const int lane = tid & 31;
    const int wid  = tid >> 5;

    // ---------------- cls[b] = argmax(gt[b, :NCLS]) (first occurrence) -------
    {
        float bv = -1e30f; int bi = 0;
        const float* g = gt + (size_t)b * NCLS_;
        for (int i = tid; i < NCLS_; i += THREADS_) {
            float v = g[i];
            if (v > bv) { bv = v; bi = i; }
        }
        sval[tid] = bv; sidx[tid] = bi;
        __syncthreads();
        for (int s = THREADS_ / 2; s > 0; s >>= 1) {
            if (tid < s) {
                float ov = sval[tid + s]; int oi = sidx[tid + s];
                if (ov > sval[tid] || (ov == sval[tid] && oi < sidx[tid])) {
                    sval[tid] = ov; sidx[tid] = oi;
                }
            }
            __syncthreads();
        }
        if (tid == 0) s_cls = sidx[0];
        __syncthreads();
    }
    const int cls = s_cls;

    // ---------------- phase 2: spatial argmax of x[b, :, :, c] ---------------
    const size_t base = (size_t)b * HWN_ * C_ + c;
    const float* xb = x + base;

    float maxv = -1e30f;
    int   amax = 0;
    #pragma unroll 4
    for (int hw = 0; hw < HWN_; ++hw) {
        float v = __ldg(xb + (size_t)hw * C_);
        if (v > maxv) { maxv = v; amax = hw; }
    }

    int hh = amax / W_;
    int ww = amax - hh * W_;
    if (maxv == 0.0f) { hh = H_; ww = W_; }          // sentinel index = shape-1 = 14
    const int plane = (hh * (W_ + 1) + ww) * HWN_;   // t_p plane base offset

    // ------------- warp-cooperative staging of t_p planes into smem ----------
    // Each warp fills the 32 rows belonging to its own lanes; coalesced loads.
    for (int j = 0; j < 32; ++j) {
        int pb = __shfl_sync(0xffffffffu, plane, j);
        const float* src = t_p + pb;
        float* dst = smem_t + (size_t)(wid * 32 + j) * ROWSTRIDE_;
        for (int k = lane; k < HWN_; k += 32)
            dst[k] = __ldg(src + k);
    }
    __syncwarp();

    // ---------------- phase 3: fused elementwise + 3 outputs ----------------
    const float* ctb = ct + (size_t)cls * HWN_ * C_ + c;
    const size_t plane_sz = (size_t)B_ * HWN_ * C_;
    float* om = out;                 // masked
    float* ox = out + plane_sz;      // x passthrough
    float* ot = out + 2 * plane_sz;  // templates
    const float* row = smem_t + (size_t)tid * ROWSTRIDE_;

    #pragma unroll 4
    for (int hw = 0; hw < HWN_; ++hw) {
        size_t off = base + (size_t)hw * C_;
        float xv = __ldg(x + off);
        float tv = row[hw];
        float cv = __ldg(ctb + (size_t)hw * C_);
        float m  = fmaxf(xv * tv, 0.0f) * cv;
        om[off] = m;
        ox[off] = xv;
        ot[off] = tv;
    }
}

extern "C" void kernel_launch(void* const* d_in, const int* in_sizes, int n_in,
                              void* d_out, int out_size) {
    const float* x  = (const float*)d_in[0];
    const float* gt = (const float*)d_in[1];
    const float* tp = (const float*)d_in[2];
    const float* ct = (const float*)d_in[3];
    float* out = (float*)d_out;

    const int smem = CCHUNK_ * ROWSTRIDE_ * sizeof(float);   // 100,864 B
    cudaFuncSetAttribute(fused_masked_kernel,
                         cudaFuncAttributeMaxDynamicSharedMemorySize, smem);

    dim3 grid(C_ / CCHUNK_, B_);     // (4, 128)
    fused_masked_kernel<<<grid, THREADS_, smem>>>(x, gt, tp, ct, out);
}

// round 2
// speedup vs baseline: 3.0380x; 3.0380x over previous
#include <cuda_runtime.h>
#include <cuda_bf16.h>

#define B_    128
#define H_    14
#define W_    14
#define C_    512
#define NCLS_ 200
#define HWN_  196            // H*W
#define HWTILE_ 28           // 196 = 7 * 28
#define NTILES_ 7

// scratch (static device arrays are allowed; cudaMalloc is not)
__device__ int g_plane[B_ * C_];   // per (b,c): flat offset of t_p plane
__device__ int g_cls[B_];          // per b: argmax class

// ---------------------------------------------------------------------------
// Kernel 1: cls[b] = argmax(gt[b, :200]) — one warp per batch row
// ---------------------------------------------------------------------------
__global__ void cls_kernel(const float* __restrict__ gt) {
    const int b = blockIdx.x;
    const int lane = threadIdx.x;
    const float* g = gt + (size_t)b * NCLS_;

    float bv = -1e30f; int bi = NCLS_;
    for (int i = lane; i < NCLS_; i += 32) {
        float v = g[i];
        if (v > bv) { bv = v; bi = i; }
    }
    #pragma unroll
    for (int s = 16; s > 0; s >>= 1) {
        float ov = __shfl_down_sync(0xffffffffu, bv, s);
        int   oi = __shfl_down_sync(0xffffffffu, bi, s);
        if (ov > bv || (ov == bv && oi < bi)) { bv = ov; bi = oi; }
    }
    if (lane == 0) g_cls[b] = bi;
}

// ---------------------------------------------------------------------------
// Kernel 2: per-(b,c) spatial argmax of x -> plane index into t_p
// block = 512 threads: 128 channels x 4 hw-groups (49 positions each)
// grid  = (C/128, B)
// ---------------------------------------------------------------------------
__global__ __launch_bounds__(512)
void argmax_kernel(const float* __restrict__ x) {
    __shared__ float sv[512];
    __shared__ int   si[512];

    const int tid = threadIdx.x;
    const int cl  = tid & 127;          // channel within chunk
    const int gpp = tid >> 7;           // hw group 0..3
    const int c   = blockIdx.x * 128 + cl;
    const int b   = blockIdx.y;

    const float* xb = x + (size_t)b * HWN_ * C_ + c;

    float maxv = -1e30f; int amax = 0;
    const int hw0 = gpp * 49;
    #pragma unroll 7
    for (int k = 0; k < 49; ++k) {
        int hw = hw0 + k;
        float v = __ldg(xb + (size_t)hw * C_);
        if (v > maxv) { maxv = v; amax = hw; }
    }
    sv[tid] = maxv; si[tid] = amax;
    __syncthreads();

    if (gpp == 0) {
        float bv = sv[cl]; int bi = si[cl];
        #pragma unroll
        for (int g2 = 1; g2 < 4; ++g2) {
            float ov = sv[g2 * 128 + cl];
            int   oi = si[g2 * 128 + cl];
            if (ov > bv) { bv = ov; bi = oi; }     // lower group = lower hw wins ties
        }
        int hh = bi / W_;
        int ww = bi - hh * W_;
        if (bv == 0.0f) { hh = H_; ww = W_; }      // sentinel
        g_plane[b * C_ + c] = (hh * (W_ + 1) + ww) * HWN_;
    }
}

// ---------------------------------------------------------------------------
// Kernel 3: fused elementwise over an hw-tile
// block = 128 threads (one channel each); grid = (C/128, B, 7 tiles)
// smem  = 128 x 29 floats (stride 29 -> conflict-free)
// ---------------------------------------------------------------------------
__global__ __launch_bounds__(128)
void ewise_kernel(const float* __restrict__ x,
                  const float* __restrict__ t_p,
                  const float* __restrict__ ct,
                  float* __restrict__ out) {
    __shared__ float smem_t[128 * 29];

    const int tid  = threadIdx.x;
    const int lane = tid & 31;
    const int wid  = tid >> 5;
    const int c    = blockIdx.x * 128 + tid;
    const int b    = blockIdx.y;
    const int hw0  = blockIdx.z * HWTILE_;

    const int cls   = __ldg(&g_cls[b]);
    const int plane = __ldg(&g_plane[b * C_ + c]);

    // warp-cooperative staging: 28 contiguous floats of each lane's plane
    #pragma unroll 8
    for (int j = 0; j < 32; ++j) {
        int pb = __shfl_sync(0xffffffffu, plane, j);
        if (lane < HWTILE_)
            smem_t[(wid * 32 + j) * 29 + lane] = __ldg(t_p + pb + hw0 + lane);
    }
    __syncwarp();

    const size_t base = (size_t)b * HWN_ * C_ + (size_t)hw0 * C_ + c;
    const float* xi  = x + base;
    const float* cti = ct + (size_t)cls * HWN_ * C_ + (size_t)hw0 * C_ + c;
    const size_t plane_sz = (size_t)B_ * HWN_ * C_;
    float* om = out + base;
    float* ox = out + plane_sz + base;
    float* ot = out + 2 * plane_sz + base;
    const float* row = smem_t + tid * 29;

    #pragma unroll 7
    for (int k = 0; k < HWTILE_; ++k) {
        size_t off = (size_t)k * C_;
        float xv = __ldg(xi + off);
        float tv = row[k];
        float cv = __ldg(cti + off);
        float m  = fmaxf(xv * tv, 0.0f) * cv;
        om[off] = m;
        ox[off] = xv;
        ot[off] = tv;
    }
}

extern "C" void kernel_launch(void* const* d_in, const int* in_sizes, int n_in,
                              void* d_out, int out_size) {
    const float* x  = (const float*)d_in[0];
    const float* gt = (const float*)d_in[1];
    const float* tp = (const float*)d_in[2];
    const float* ct = (const float*)d_in[3];
    float* out = (float*)d_out;

    cls_kernel<<<B_, 32>>>(gt);
    argmax_kernel<<<dim3(C_ / 128, B_), 512>>>(x);
    ewise_kernel<<<dim3(C_ / 128, B_, NTILES_), 128>>>(x, tp, ct, out);
}

// round 3
// speedup vs baseline: 3.3952x; 1.1176x over previous
#include <cuda_runtime.h>
#include <cuda_bf16.h>

#define B_    128
#define H_    14
#define W_    14
#define C_    512
#define NCLS_ 200
#define HWN_  196
#define TILE_ 28            // hw tile
#define NT_   7             // 196 / 28
#define CCH_  64            // channels per block
#define THR_  256           // 64 channels x 4 hw-groups

__device__ int g_cls[B_];

// ---------------------------------------------------------------------------
// Kernel 1: cls[b] = argmax(gt[b,:200]); warp per batch, 4 blocks x 1024 thr
// ---------------------------------------------------------------------------
__global__ __launch_bounds__(1024)
void cls_kernel(const float* __restrict__ gt) {
    const int w    = threadIdx.x >> 5;
    const int lane = threadIdx.x & 31;
    const int b    = blockIdx.x * 32 + w;
    if (b >= B_) return;

    const float* g = gt + (size_t)b * NCLS_;
    float bv = -1e30f; int bi = NCLS_;
    for (int i = lane; i < NCLS_; i += 32) {
        float v = g[i];
        if (v > bv) { bv = v; bi = i; }
    }
    #pragma unroll
    for (int s = 16; s > 0; s >>= 1) {
        float ov = __shfl_down_sync(0xffffffffu, bv, s);
        int   oi = __shfl_down_sync(0xffffffffu, bi, s);
        if (ov > bv || (ov == bv && oi < bi)) { bv = ov; bi = oi; }
    }
    if (lane == 0) g_cls[b] = bi;
}

// ---------------------------------------------------------------------------
// Kernel 2 (fused): spatial argmax -> template gather -> elementwise outputs
// block = 256 threads: 64 channels x 4 hw-groups; grid = (C/64, B) = 1024
// ---------------------------------------------------------------------------
__global__ __launch_bounds__(THR_)
void fused_kernel(const float* __restrict__ x,
                  const float* __restrict__ t_p,
                  const float* __restrict__ ct,
                  float* __restrict__ out) {
    __shared__ float sv[THR_];
    __shared__ int   si[THR_];
    __shared__ int   s_plane[CCH_];
    __shared__ float smem_t[CCH_ * 29];     // stride 29: conflict-free

    const int tid  = threadIdx.x;
    const int cl   = tid & (CCH_ - 1);      // channel within chunk
    const int gpp  = tid >> 6;              // hw group 0..3 (49 each)
    const int lane = tid & 31;
    const int wid  = tid >> 5;
    const int c    = blockIdx.x * CCH_ + cl;
    const int b    = blockIdx.y;

    const size_t bbase = (size_t)b * HWN_ * C_;
    const float* xb = x + bbase + c;

    // ---- phase 1: per-channel spatial argmax (4-way hw split for ILP) ----
    float maxv = -1e30f; int amax = 0;
    const int h0 = gpp * 49;
    #pragma unroll 7
    for (int k = 0; k < 49; ++k) {
        float v = __ldg(xb + (size_t)(h0 + k) * C_);
        if (v > maxv) { maxv = v; amax = h0 + k; }
    }
    sv[tid] = maxv; si[tid] = amax;
    __syncthreads();

    if (gpp == 0) {
        float bv = sv[cl]; int bi = si[cl];
        #pragma unroll
        for (int g2 = 1; g2 < 4; ++g2) {
            float ov = sv[g2 * CCH_ + cl];
            int   oi = si[g2 * CCH_ + cl];
            if (ov > bv) { bv = ov; bi = oi; }   // ascending group = first occurrence
        }
        int hh = bi / W_;
        int ww = bi - hh * W_;
        if (bv == 0.0f) { hh = H_; ww = W_; }    // sentinel
        s_plane[cl] = (hh * (W_ + 1) + ww) * HWN_;
    }
    __syncthreads();

    // ---- phase 2: tiled elementwise; x re-read hits L2 ----
    const int cls = __ldg(&g_cls[b]);
    const float* ctb = ct + (size_t)cls * HWN_ * C_ + c;
    const size_t psz = (size_t)B_ * HWN_ * C_;
    const float* row = smem_t + cl * 29;

    for (int t = 0; t < NT_; ++t) {
        const int hw0 = t * TILE_;

        // stage: 8 warps x 8 channels; lanes 0..27 load contiguous t_p floats
        #pragma unroll
        for (int j = 0; j < 8; ++j) {
            int ch = wid * 8 + j;
            if (lane < TILE_)
                smem_t[ch * 29 + lane] = __ldg(t_p + s_plane[ch] + hw0 + lane);
        }
        __syncthreads();

        #pragma unroll 7
        for (int k = 0; k < 7; ++k) {
            int hw = hw0 + gpp * 7 + k;
            size_t off = bbase + (size_t)hw * C_ + c;
            float xv = __ldg(x + off);
            float tv = row[gpp * 7 + k];
            float cv = __ldg(ctb + (size_t)hw * C_);
            float m  = fmaxf(xv * tv, 0.0f) * cv;
            out[off]           = m;
            out[psz + off]     = xv;
            out[2 * psz + off] = tv;
        }
        __syncthreads();   // protect smem_t before restage
    }
}

extern "C" void kernel_launch(void* const* d_in, const int* in_sizes, int n_in,
                              void* d_out, int out_size) {
    const float* x  = (const float*)d_in[0];
    const float* gt = (const float*)d_in[1];
    const float* tp = (const float*)d_in[2];
    const float* ct = (const float*)d_in[3];
    float* out = (float*)d_out;

    cls_kernel<<<4, 1024>>>(gt);
    fused_kernel<<<dim3(C_ / CCH_, B_), THR_>>>(x, tp, ct, out);
}